// round 16
// baseline (speedup 1.0000x reference)
#include <cuda_runtime.h>
#include <cstdint>

typedef unsigned long long ull;

#define B_     16
#define D_     4096
#define NKV    8
#define HD     128
#define SEQ    4096
#define KSPLIT 16
#define KSLICE 256
#define STAGES 4
#define GSTG   8
#define GKROW  4
#define GCOLS  512
#define GWARPS 4

// ---------------- scratch ----------------
// GEMM partials ROW-PAIR interleaved: float idx ((ks*8+p)*2N) + col*2 + e, row=2p+e
__device__ float g_attn[B_ * D_];
__device__ float g_Pq  [KSPLIT * B_ * D_];
__device__ float g_Pk  [KSPLIT * B_ * NKV * HD];
__device__ float g_Pv  [KSPLIT * B_ * NKV * HD];
__device__ float g_Po  [KSPLIT * B_ * D_];

// ---------------- packed f32x2 helpers ----------------
__device__ __forceinline__ ull ffma2(ull a, ull b, ull c) {
    ull d; asm("fma.rn.f32x2 %0,%1,%2,%3;" : "=l"(d) : "l"(a), "l"(b), "l"(c)); return d;
}
__device__ __forceinline__ ull fmul2(ull a, ull b) {
    ull d; asm("mul.rn.f32x2 %0,%1,%2;" : "=l"(d) : "l"(a), "l"(b)); return d;
}
__device__ __forceinline__ ull fadd2(ull a, ull b) {
    ull d; asm("add.rn.f32x2 %0,%1,%2;" : "=l"(d) : "l"(a), "l"(b)); return d;
}
__device__ __forceinline__ ull pack2(float x, float y) {
    ull d; asm("mov.b64 %0,{%1,%2};" : "=l"(d) : "f"(x), "f"(y)); return d;
}
__device__ __forceinline__ float2 unpack2(ull a) {
    float2 r; asm("mov.b64 {%0,%1},%2;" : "=f"(r.x), "=f"(r.y) : "l"(a)); return r;
}
__device__ __forceinline__ ull redshfl2(ull v, int m) {
    float2 f = unpack2(v);
    float x = __shfl_xor_sync(0xffffffffu, f.x, m);
    float y = __shfl_xor_sync(0xffffffffu, f.y, m);
    return fadd2(v, pack2(x, y));
}

#define CP16(dst, src) asm volatile("cp.async.cg.shared.global [%0],[%1],16;\n" :: "r"(dst), "l"(src) : "memory")
#define CPCOMMIT()     asm volatile("cp.async.commit_group;\n" ::: "memory")
#define CPWAIT3()      asm volatile("cp.async.wait_group 3;\n" ::: "memory")
#define CPWAIT6()      asm volatile("cp.async.wait_group 6;\n" ::: "memory")

// ---------------- skinny GEMM: out[16,N] = X[16,4096] @ W[4096,N] ----------------
// 128-thread blocks, 4 warps x 128 cols, cp.async 8-stage warp-private ring.
// CONFLICT-FREE weight consumption: lane reads cols lane*4 (16B contiguous per
// warp-LDS.128). Tiling: 8 row-pairs x 4 cols per lane; x enters as 4 contiguous
// broadcast LDS.128 per k-row.
__global__ void __launch_bounds__(128, 2) gemm16(const float* __restrict__ Xin,
                                                 const float* __restrict__ W0,
                                                 const float* __restrict__ W1,
                                                 const float* __restrict__ W2,
                                                 int mode)
{
    extern __shared__ char gsm[];
    float* ring = (float*)gsm;                                // [GSTG][4 warps][4k][512B] = 64KB
    ull*   xs2  = (ull*)(gsm + GSTG * GWARPS * 2048);         // [KSLICE][8 row-pairs] = 16KB

    int t = blockIdx.x, ks = blockIdx.y;
    const float* X = Xin; const float* W; float* P; int N, ct;
    if (mode == 0) {
        if (t < 8)       { W = W0; P = g_Pq; N = 4096; ct = t; }
        else if (t < 10) { W = W1; P = g_Pk; N = 1024; ct = t - 8; }
        else             { W = W2; P = g_Pv; N = 1024; ct = t - 10; }
    } else {
        W = W0; P = g_Po; N = 4096; ct = t; X = g_attn;
    }

    int tid = threadIdx.x, wid = tid >> 5, lane = tid & 31;
    int kbase = ks * KSLICE;
    int colbase = ct * GCOLS + wid * 128;

    const float* Wbase = W + (size_t)kbase * N + colbase + lane * 4;
    uint32_t wbuf0 = (uint32_t)__cvta_generic_to_shared(ring) + wid * 2048 + lane * 16;

    auto cpstage = [&](int s, int slot) {
        const float* srow = Wbase + (size_t)(s * GKROW) * N;
        uint32_t d = wbuf0 + slot * (GWARPS * 2048);
        CP16(d,        srow);
        CP16(d + 512,  srow + N);
        CP16(d + 1024, srow + 2 * (size_t)N);
        CP16(d + 1536, srow + 3 * (size_t)N);
    };

    #pragma unroll
    for (int s = 0; s < GSTG; s++) { cpstage(s, s); CPCOMMIT(); }

    // x -> row-pair ulls in smem, layout [k][p]
    #pragma unroll
    for (int kk = 0; kk < 2; kk++) {
        int k = tid * 2 + kk;
        #pragma unroll
        for (int p = 0; p < 8; p++) {
            float e0 = X[(2 * p) * 4096 + kbase + k];
            float e1 = X[(2 * p + 1) * 4096 + kbase + k];
            xs2[(size_t)k * 8 + p] = pack2(e0, e1);
        }
    }
    __syncthreads();

    ull acc[8][4] = {};    // acc[p][c] = (out[2p][col c], out[2p+1][col c]), col = colbase+lane*4+c

    #pragma unroll 1
    for (int s = 0; s < KSLICE / GKROW; s++) {       // 64 stages
        CPWAIT6();
        __syncwarp();
        int slot = s & (GSTG - 1);
        const float* wsp = ring + (size_t)(slot * GWARPS + wid) * 512 + lane * 4;
        const ull* xsp = xs2 + (size_t)s * (GKROW * 8);
        #pragma unroll
        for (int k = 0; k < GKROW; k++) {
            float4 w4 = *(const float4*)(wsp + k * 128);     // conflict-free LDS.128
            ull ws0 = pack2(w4.x, w4.x), ws1 = pack2(w4.y, w4.y);
            ull ws2 = pack2(w4.z, w4.z), ws3 = pack2(w4.w, w4.w);
            const ull* xk = xsp + k * 8;
            ulonglong2 x01 = *(const ulonglong2*)(xk);       // broadcast LDS.128 x4
            ulonglong2 x23 = *(const ulonglong2*)(xk + 2);
            ulonglong2 x45 = *(const ulonglong2*)(xk + 4);
            ulonglong2 x67 = *(const ulonglong2*)(xk + 6);
            ull xv[8] = {x01.x, x01.y, x23.x, x23.y, x45.x, x45.y, x67.x, x67.y};
            #pragma unroll
            for (int p = 0; p < 8; p++) {
                acc[p][0] = ffma2(xv[p], ws0, acc[p][0]);
                acc[p][1] = ffma2(xv[p], ws1, acc[p][1]);
                acc[p][2] = ffma2(xv[p], ws2, acc[p][2]);
                acc[p][3] = ffma2(xv[p], ws3, acc[p][3]);
            }
        }
        if (s + GSTG < KSLICE / GKROW) cpstage(s + GSTG, slot);
        CPCOMMIT();
    }

    // store row-pair interleaved: float idx = (ks*8+p)*2N + col*2 + e
    #pragma unroll
    for (int p = 0; p < 8; p++) {
        float* o = P + ((size_t)ks * 8 + p) * (2 * (size_t)N) + (size_t)(colbase + lane * 4) * 2;
        ulonglong2 s1; s1.x = acc[p][0]; s1.y = acc[p][1];
        ulonglong2 s2; s2.x = acc[p][2]; s2.y = acc[p][3];
        *(ulonglong2*)(o)     = s1;
        *(ulonglong2*)(o + 4) = s2;
    }
}

// ---------------- attention: warp-per-key, conflict-free, fused q/k/v norm ----------------
// grid (8,16), 512 threads (16 warps). Warp w handles keys i*32+2w, i*32+2w+1.
// Lane owns dims lane*4..+3 -> all K/V smem reads are conflict-free LDS.128.
__global__ void __launch_bounds__(512, 1) attention(const float* __restrict__ CK,
                                                    const float* __restrict__ CV)
{
    extern __shared__ float sm[];
    float* ksm  = sm;                        // [STAGES][32][128]
    float* vsm  = sm + STAGES * 32 * 128;    // [STAGES][32][128]
    float* part = vsm + STAGES * 32 * 128;   // [16][512]
    float* psum = part + 16 * 512;           // [16][4]
    float* knvn = psum + 64;                 // [2][128]
    float* qsm  = knvn + 256;                // [4][128]
    __shared__ float redq[16];
    __shared__ float redk[8];

    int g = blockIdx.x, b = blockIdx.y;
    int tid = threadIdx.x, w = tid >> 5, lane = tid & 31;
    int r = tid >> 7, d = tid & 127;
    int pb = b >> 1, eb = b & 1;

    // ---- fused combine + l2norm of q, kn, vn ----
    float qv = 0.f;
    {
        const float* pq = g_Pq + (size_t)pb * 8192 + (size_t)((g * 4 + r) * 128 + d) * 2 + eb;
        #pragma unroll
        for (int s = 0; s < KSPLIT; s++) qv += pq[(size_t)s * 8 * 8192];
    }
    float kv = 0.f;
    if (r < 2) {
        const float* pkv = (r == 0 ? g_Pk : g_Pv) + (size_t)pb * 2048 + (size_t)(g * 128 + d) * 2 + eb;
        #pragma unroll
        for (int s = 0; s < KSPLIT; s++) kv += pkv[(size_t)s * 8 * 2048];
    }
    float s1 = qv * qv;
    float s2 = kv * kv;
    #pragma unroll
    for (int m = 16; m >= 1; m >>= 1) {
        s1 += __shfl_xor_sync(0xffffffffu, s1, m);
        s2 += __shfl_xor_sync(0xffffffffu, s2, m);
    }
    if (lane == 0) { redq[w] = s1; if (w < 8) redk[w] = s2; }
    __syncthreads();
    {
        float qsum = redq[r * 4] + redq[r * 4 + 1] + redq[r * 4 + 2] + redq[r * 4 + 3];
        qsm[r * 128 + d] = qv * rsqrtf(qsum * (1.0f / 128.0f) + 1e-6f);
        if (r == 0) {
            float ksum = redk[0] + redk[1] + redk[2] + redk[3];
            knvn[d] = kv * rsqrtf(ksum * (1.0f / 128.0f) + 1e-6f);
        }
        if (r == 1) knvn[128 + d] = kv;   // v: no norm
    }
    __syncthreads();

    const float sc = 0.08838834764831845f;   // 1/sqrt(128)
    ull q2[4][2];
    #pragma unroll
    for (int r2 = 0; r2 < 4; r2++) {
        float4 qq = *(const float4*)&qsm[r2 * 128 + lane * 4];
        q2[r2][0] = pack2(qq.x * sc, qq.y * sc);
        q2[r2][1] = pack2(qq.z * sc, qq.w * sc);
    }

    const float* Kb = CK + (size_t)b * (SEQ * NKV * HD) + g * HD;
    const float* Vb = CV + (size_t)b * (SEQ * NKV * HD) + g * HD;
    int half = lane >> 4, sub = lane & 15;
    int H = w * 2 + half;
    uint32_t kdst0 = (uint32_t)__cvta_generic_to_shared(ksm + (size_t)H * 128 + sub * 8);
    uint32_t vdst0 = (uint32_t)__cvta_generic_to_shared(vsm + (size_t)H * 128 + sub * 8);

    auto copy_stage = [&](int st, int step) {
        int k = step * 32 + H;
        const float* kp = Kb + (size_t)k * (NKV * HD) + sub * 8;
        const float* vp = Vb + (size_t)k * (NKV * HD) + sub * 8;
        uint32_t kd = kdst0 + st * (32 * 128 * 4);
        uint32_t vd = vdst0 + st * (32 * 128 * 4);
        CP16(kd, kp);       CP16(kd + 16, kp + 4);
        CP16(vd, vp);       CP16(vd + 16, vp + 4);
    };

    #pragma unroll
    for (int s = 0; s < STAGES; s++) { copy_stage(s, s); CPCOMMIT(); }

    ull acc[4][2] = {};
    float ssum[4] = {0.f, 0.f, 0.f, 0.f};

    auto process = [&](ulonglong2 kx, ulonglong2 vx) {
        float p[4];
        #pragma unroll
        for (int r2 = 0; r2 < 4; r2++) {
            ull tq = fmul2(q2[r2][0], kx.x);
            tq = ffma2(q2[r2][1], kx.y, tq);
            float2 f = unpack2(tq);
            p[r2] = f.x + f.y;
        }
        ull p01 = pack2(p[0], p[1]), p23 = pack2(p[2], p[3]);
        #pragma unroll
        for (int m = 1; m <= 16; m <<= 1) {
            p01 = redshfl2(p01, m);
            p23 = redshfl2(p23, m);
        }
        float2 fa = unpack2(p01), fc = unpack2(p23);
        float w0 = __expf(fa.x - 16.0f);
        float w1 = __expf(fa.y - 16.0f);
        float w2 = __expf(fc.x - 16.0f);
        float w3 = __expf(fc.y - 16.0f);
        ssum[0] += w0; ssum[1] += w1; ssum[2] += w2; ssum[3] += w3;
        acc[0][0] = ffma2(pack2(w0, w0), vx.x, acc[0][0]);
        acc[0][1] = ffma2(pack2(w0, w0), vx.y, acc[0][1]);
        acc[1][0] = ffma2(pack2(w1, w1), vx.x, acc[1][0]);
        acc[1][1] = ffma2(pack2(w1, w1), vx.y, acc[1][1]);
        acc[2][0] = ffma2(pack2(w2, w2), vx.x, acc[2][0]);
        acc[2][1] = ffma2(pack2(w2, w2), vx.y, acc[2][1]);
        acc[3][0] = ffma2(pack2(w3, w3), vx.x, acc[3][0]);
        acc[3][1] = ffma2(pack2(w3, w3), vx.y, acc[3][1]);
    };

    #pragma unroll 1
    for (int i = 0; i < SEQ / 32 - 1; i++) {       // 0..126
        CPWAIT3();
        int st = i & (STAGES - 1);
        const float* rowA = ksm + (size_t)(st * 32 + 2 * w) * 128 + lane * 4;
        ulonglong2 kA = *(const ulonglong2*)rowA;                      // conflict-free
        ulonglong2 kB = *(const ulonglong2*)(rowA + 128);
        const float* vrowA = vsm + (size_t)(st * 32 + 2 * w) * 128 + lane * 4;
        ulonglong2 vA = *(const ulonglong2*)vrowA;
        ulonglong2 vB = *(const ulonglong2*)(vrowA + 128);

        if (i + STAGES < SEQ / 32) copy_stage(st, i + STAGES);
        CPCOMMIT();

        process(kA, vA);
        process(kB, vB);
    }
    // peeled last iteration (i = 127): warp 15's second key is the NEW token
    {
        CPWAIT3();
        int st = 3;
        const float* rowA = ksm + (size_t)(st * 32 + 2 * w) * 128 + lane * 4;
        ulonglong2 kA = *(const ulonglong2*)rowA;
        const float* vrowA = vsm + (size_t)(st * 32 + 2 * w) * 128 + lane * 4;
        ulonglong2 vA = *(const ulonglong2*)vrowA;
        ulonglong2 kB, vB;
        if (w == 15) {
            kB = *(const ulonglong2*)&knvn[lane * 4];
            vB = *(const ulonglong2*)&knvn[128 + lane * 4];
        } else {
            kB = *(const ulonglong2*)(rowA + 128);
            vB = *(const ulonglong2*)(vrowA + 128);
        }
        process(kA, vA);
        process(kB, vB);
    }

    // dump per-warp partials
    #pragma unroll
    for (int r2 = 0; r2 < 4; r2++) {
        *(ull*)&part[(size_t)w * 512 + r2 * 128 + lane * 4]     = acc[r2][0];
        *(ull*)&part[(size_t)w * 512 + r2 * 128 + lane * 4 + 2] = acc[r2][1];
        if (lane == 0) psum[w * 4 + r2] = ssum[r2];
    }
    __syncthreads();

    float tot = 0.f, ts = 0.f;
    #pragma unroll
    for (int h2 = 0; h2 < 16; h2++) {
        tot += part[(size_t)h2 * 512 + tid];
        ts  += psum[h2 * 4 + r];
    }
    g_attn[(size_t)b * 4096 + g * 512 + tid] = tot / ts;
}

// ---------------- final combine of wo K-split partials ----------------
__global__ void __launch_bounds__(256) combine_out(float* __restrict__ out)
{
    int e = blockIdx.x * 256 + threadIdx.x;
    int b = e >> 12, col = e & 4095;
    const float* p = g_Po + (size_t)(b >> 1) * 8192 + (size_t)col * 2 + (b & 1);
    float v = 0.f;
    #pragma unroll
    for (int ks = 0; ks < KSPLIT; ks++) v += p[(size_t)ks * 8 * 8192];
    out[e] = v;
}

// ---------------- launch ----------------
extern "C" void kernel_launch(void* const* d_in, const int* in_sizes, int n_in,
                              void* d_out, int out_size)
{
    const float* x  = (const float*)d_in[0];
    const float* wq = (const float*)d_in[1];
    const float* wk = (const float*)d_in[2];
    const float* wv = (const float*)d_in[3];
    const float* wo = (const float*)d_in[4];
    const float* ck = (const float*)d_in[5];
    const float* cv = (const float*)d_in[6];

    const int attn_smem = (STAGES * 32 * 128 * 2 + 16 * 512 + 64 + 256 + 512) * 4;  // ~167KB
    const int gemm_smem = GSTG * GWARPS * 2048 + KSLICE * 8 * 8;                    // 64KB + 16KB
    static int smem_set = 0;
    if (!smem_set) {
        cudaFuncSetAttribute(attention, cudaFuncAttributeMaxDynamicSharedMemorySize, attn_smem);
        cudaFuncSetAttribute(gemm16, cudaFuncAttributeMaxDynamicSharedMemorySize, gemm_smem);
        smem_set = 1;
    }

    gemm16<<<dim3(12, KSPLIT), 128, gemm_smem>>>(x, wq, wk, wv, 0);
    attention<<<dim3(8, 16), 512, attn_smem>>>(ck, cv);
    gemm16<<<dim3(8, KSPLIT), 128, gemm_smem>>>(x, wo, wo, wo, 1);
    combine_out<<<256, 256>>>((float*)d_out);
}

// round 17
// speedup vs baseline: 1.0025x; 1.0025x over previous
#include <cuda_runtime.h>
#include <cstdint>

typedef unsigned long long ull;

#define B_     16
#define D_     4096
#define NKV    8
#define HD     128
#define SEQ    4096
#define KSPLIT 16
#define KSLICE 256
#define STAGES 4
#define NSTG   5          // bulk-copy ring stages
#define SROWS  8          // k-rows per stage (16KB)
#define GCOLS  512

// ---------------- scratch ----------------
// GEMM partials ROW-PAIR interleaved: float idx ((ks*8+p)*2N) + col*2 + e, row=2p+e
__device__ float g_attn[B_ * D_];
__device__ float g_Pq  [KSPLIT * B_ * D_];
__device__ float g_Pk  [KSPLIT * B_ * NKV * HD];
__device__ float g_Pv  [KSPLIT * B_ * NKV * HD];
__device__ float g_Po  [KSPLIT * B_ * D_];

// ---------------- packed f32x2 helpers ----------------
__device__ __forceinline__ ull ffma2(ull a, ull b, ull c) {
    ull d; asm("fma.rn.f32x2 %0,%1,%2,%3;" : "=l"(d) : "l"(a), "l"(b), "l"(c)); return d;
}
__device__ __forceinline__ ull fmul2(ull a, ull b) {
    ull d; asm("mul.rn.f32x2 %0,%1,%2;" : "=l"(d) : "l"(a), "l"(b)); return d;
}
__device__ __forceinline__ ull fadd2(ull a, ull b) {
    ull d; asm("add.rn.f32x2 %0,%1,%2;" : "=l"(d) : "l"(a), "l"(b)); return d;
}
__device__ __forceinline__ ull pack2(float x, float y) {
    ull d; asm("mov.b64 %0,{%1,%2};" : "=l"(d) : "f"(x), "f"(y)); return d;
}
__device__ __forceinline__ float2 unpack2(ull a) {
    float2 r; asm("mov.b64 {%0,%1},%2;" : "=f"(r.x), "=f"(r.y) : "l"(a)); return r;
}
__device__ __forceinline__ ull redshfl2(ull v, int m) {
    float2 f = unpack2(v);
    float x = __shfl_xor_sync(0xffffffffu, f.x, m);
    float y = __shfl_xor_sync(0xffffffffu, f.y, m);
    return fadd2(v, pack2(x, y));
}

#define CP16(dst, src) asm volatile("cp.async.cg.shared.global [%0],[%1],16;\n" :: "r"(dst), "l"(src) : "memory")
#define CPCOMMIT()     asm volatile("cp.async.commit_group;\n" ::: "memory")
#define CPWAIT3()      asm volatile("cp.async.wait_group 3;\n" ::: "memory")

#define BULK2K(dst, src, mbar) \
    asm volatile("cp.async.bulk.shared::cta.global.mbarrier::complete_tx::bytes [%0], [%1], 2048, [%2];" \
                 :: "r"(dst), "l"(src), "r"(mbar) : "memory")

#define MBARRIER_INIT(mbar, cnt) \
    asm volatile("mbarrier.init.shared.b64 [%0], %1;" :: "r"((uint32_t)(mbar)), "r"((uint32_t)(cnt)) : "memory")
#define MBARRIER_EXPECT_TX(mbar, tx) \
    asm volatile("mbarrier.arrive.expect_tx.shared.b64 _, [%0], %1;" :: "r"((uint32_t)(mbar)), "r"((uint32_t)(tx)) : "memory")
#define MBARRIER_ARRIVE(mbar) \
    asm volatile("mbarrier.arrive.shared.b64 _, [%0];" :: "r"((uint32_t)(mbar)) : "memory")
#define MBARRIER_WAIT_PARITY(mbar, parity) do { \
    uint32_t _m = (uint32_t)(mbar); uint32_t _p = (uint32_t)(parity); uint32_t _done; \
    asm volatile("{\n\t.reg .pred p;\n\t" \
        "mbarrier.try_wait.parity.acquire.cta.shared::cta.b64 p, [%1], %2;\n\t" \
        "selp.b32 %0, 1, 0, p;\n\t}" : "=r"(_done) : "r"(_m), "r"(_p) : "memory"); \
    if (!_done) { \
        asm volatile("{\n\t.reg .pred P1;\n\t" \
            "WL_%=:\n\t" \
            "mbarrier.try_wait.parity.acquire.cta.shared::cta.b64 P1, [%0], %1, 0x989680;\n\t" \
            "@P1 bra.uni WD_%=;\n\t" \
            "bra.uni WL_%=;\n\t" \
            "WD_%=:\n\t}" :: "r"(_m), "r"(_p) : "memory"); \
    } \
} while (0)

// ---------------- skinny GEMM: out[16,N] = X[16,4096] @ W[4096,N] ----------------
// Warp-specialized bulk-copy pipeline: warp 4 (lane 0) drives a 5-stage ring of
// 16KB stages (8 k-rows x 512 cols) via cp.async.bulk + mbarrier tx; warps 0-3
// consume (row-pair packed FFMA2, conflict-free weight LDS).
__global__ void __launch_bounds__(160, 1) gemm16(const float* __restrict__ Xin,
                                                 const float* __restrict__ W0,
                                                 const float* __restrict__ W1,
                                                 const float* __restrict__ W2,
                                                 int mode)
{
    extern __shared__ char gsm[];
    float* ring = (float*)gsm;                                 // [NSTG][SROWS][512] = 80KB
    ull*   xs2  = (ull*)(gsm + NSTG * SROWS * 2048);           // [KSLICE][8] = 16KB
    uint32_t mb0 = (uint32_t)__cvta_generic_to_shared(gsm + NSTG * SROWS * 2048 + KSLICE * 64);
    // full[s] = mb0 + s*16, empty[s] = mb0 + s*16 + 8

    int t = blockIdx.x, ks = blockIdx.y;
    const float* X = Xin; const float* W; float* P; int N, ct;
    if (mode == 0) {
        if (t < 8)       { W = W0; P = g_Pq; N = 4096; ct = t; }
        else if (t < 10) { W = W1; P = g_Pk; N = 1024; ct = t - 8; }
        else             { W = W2; P = g_Pv; N = 1024; ct = t - 10; }
    } else {
        W = W0; P = g_Po; N = 4096; ct = t; X = g_attn;
    }

    int tid = threadIdx.x, wid = tid >> 5, lane = tid & 31;
    int kbase = ks * KSLICE;
    int colbase = ct * GCOLS;

    if (tid == 0) {
        #pragma unroll
        for (int s = 0; s < NSTG; s++) {
            MBARRIER_INIT(mb0 + s * 16, 1);        // full: expect_tx arrival
            MBARRIER_INIT(mb0 + s * 16 + 8, 4);    // empty: 4 consumer warps
        }
    }
    // x -> row-pair ulls in smem, layout [k][p]
    for (int idx = tid; idx < KSLICE * 8; idx += 160) {
        int k = idx >> 3, p = idx & 7;
        float e0 = X[(2 * p) * 4096 + kbase + k];
        float e1 = X[(2 * p + 1) * 4096 + kbase + k];
        xs2[idx] = pack2(e0, e1);
    }
    __syncthreads();

    const int NSTEP = KSLICE / SROWS;     // 32

    if (wid == 4) {
        // ---- producer ----
        if (lane == 0) {
            const float* Wb = W + (size_t)kbase * N + colbase;
            uint32_t rbase = (uint32_t)__cvta_generic_to_shared(ring);
            int slot = 0, phase = 1;
            for (int s = 0; s < NSTEP; s++) {
                MBARRIER_WAIT_PARITY(mb0 + slot * 16 + 8, phase);
                uint32_t fullb = mb0 + slot * 16;
                MBARRIER_EXPECT_TX(fullb, SROWS * 2048);
                const float* src = Wb + (size_t)(s * SROWS) * N;
                uint32_t dst = rbase + slot * (SROWS * 2048);
                #pragma unroll
                for (int r = 0; r < SROWS; r++)
                    BULK2K(dst + r * 2048, src + (size_t)r * N, fullb);
                if (++slot == NSTG) { slot = 0; phase ^= 1; }
            }
        }
        return;
    }

    // ---- consumers: warps 0-3, each owns cols wid*128 + lane*4 ----
    ull acc[8][4] = {};
    int slot = 0, phase = 0;
    #pragma unroll 1
    for (int s = 0; s < NSTEP; s++) {
        MBARRIER_WAIT_PARITY(mb0 + slot * 16, phase);
        const float* wsp = ring + (size_t)slot * (SROWS * 512) + wid * 128 + lane * 4;
        const ull* xsp = xs2 + (size_t)s * (SROWS * 8);
        #pragma unroll
        for (int k = 0; k < SROWS; k++) {
            float4 w4 = *(const float4*)(wsp + k * 512);     // conflict-free LDS.128
            ull ws0 = pack2(w4.x, w4.x), ws1 = pack2(w4.y, w4.y);
            ull ws2 = pack2(w4.z, w4.z), ws3 = pack2(w4.w, w4.w);
            const ull* xk = xsp + k * 8;
            ulonglong2 x01 = *(const ulonglong2*)(xk);       // broadcast LDS.128 x4
            ulonglong2 x23 = *(const ulonglong2*)(xk + 2);
            ulonglong2 x45 = *(const ulonglong2*)(xk + 4);
            ulonglong2 x67 = *(const ulonglong2*)(xk + 6);
            ull xv[8] = {x01.x, x01.y, x23.x, x23.y, x45.x, x45.y, x67.x, x67.y};
            #pragma unroll
            for (int p = 0; p < 8; p++) {
                acc[p][0] = ffma2(xv[p], ws0, acc[p][0]);
                acc[p][1] = ffma2(xv[p], ws1, acc[p][1]);
                acc[p][2] = ffma2(xv[p], ws2, acc[p][2]);
                acc[p][3] = ffma2(xv[p], ws3, acc[p][3]);
            }
        }
        __syncwarp();
        if (lane == 0) MBARRIER_ARRIVE(mb0 + slot * 16 + 8);
        if (++slot == NSTG) { slot = 0; phase ^= 1; }
    }

    // store row-pair interleaved: float idx = (ks*8+p)*2N + col*2 + e
    #pragma unroll
    for (int p = 0; p < 8; p++) {
        float* o = P + ((size_t)ks * 8 + p) * (2 * (size_t)N) + (size_t)(colbase + wid * 128 + lane * 4) * 2;
        ulonglong2 s1; s1.x = acc[p][0]; s1.y = acc[p][1];
        ulonglong2 s2; s2.x = acc[p][2]; s2.y = acc[p][3];
        *(ulonglong2*)(o)     = s1;
        *(ulonglong2*)(o + 4) = s2;
    }
}

// ---------------- attention: warp-per-key, conflict-free, fused q/k/v norm ----------------
__global__ void __launch_bounds__(512, 1) attention(const float* __restrict__ CK,
                                                    const float* __restrict__ CV)
{
    extern __shared__ float sm[];
    float* ksm  = sm;                        // [STAGES][32][128]
    float* vsm  = sm + STAGES * 32 * 128;    // [STAGES][32][128]
    float* part = vsm + STAGES * 32 * 128;   // [16][512]
    float* psum = part + 16 * 512;           // [16][4]
    float* knvn = psum + 64;                 // [2][128]
    float* qsm  = knvn + 256;                // [4][128]
    __shared__ float redq[16];
    __shared__ float redk[8];

    int g = blockIdx.x, b = blockIdx.y;
    int tid = threadIdx.x, w = tid >> 5, lane = tid & 31;
    int r = tid >> 7, d = tid & 127;
    int pb = b >> 1, eb = b & 1;

    // ---- fused combine + l2norm of q, kn, vn ----
    float qv = 0.f;
    {
        const float* pq = g_Pq + (size_t)pb * 8192 + (size_t)((g * 4 + r) * 128 + d) * 2 + eb;
        #pragma unroll
        for (int s = 0; s < KSPLIT; s++) qv += pq[(size_t)s * 8 * 8192];
    }
    float kv = 0.f;
    if (r < 2) {
        const float* pkv = (r == 0 ? g_Pk : g_Pv) + (size_t)pb * 2048 + (size_t)(g * 128 + d) * 2 + eb;
        #pragma unroll
        for (int s = 0; s < KSPLIT; s++) kv += pkv[(size_t)s * 8 * 2048];
    }
    float s1 = qv * qv;
    float s2 = kv * kv;
    #pragma unroll
    for (int m = 16; m >= 1; m >>= 1) {
        s1 += __shfl_xor_sync(0xffffffffu, s1, m);
        s2 += __shfl_xor_sync(0xffffffffu, s2, m);
    }
    if (lane == 0) { redq[w] = s1; if (w < 8) redk[w] = s2; }
    __syncthreads();
    {
        float qsum = redq[r * 4] + redq[r * 4 + 1] + redq[r * 4 + 2] + redq[r * 4 + 3];
        qsm[r * 128 + d] = qv * rsqrtf(qsum * (1.0f / 128.0f) + 1e-6f);
        if (r == 0) {
            float ksum = redk[0] + redk[1] + redk[2] + redk[3];
            knvn[d] = kv * rsqrtf(ksum * (1.0f / 128.0f) + 1e-6f);
        }
        if (r == 1) knvn[128 + d] = kv;   // v: no norm
    }
    __syncthreads();

    const float sc = 0.08838834764831845f;   // 1/sqrt(128)
    ull q2[4][2];
    #pragma unroll
    for (int r2 = 0; r2 < 4; r2++) {
        float4 qq = *(const float4*)&qsm[r2 * 128 + lane * 4];
        q2[r2][0] = pack2(qq.x * sc, qq.y * sc);
        q2[r2][1] = pack2(qq.z * sc, qq.w * sc);
    }

    const float* Kb = CK + (size_t)b * (SEQ * NKV * HD) + g * HD;
    const float* Vb = CV + (size_t)b * (SEQ * NKV * HD) + g * HD;
    int half = lane >> 4, sub = lane & 15;
    int H = w * 2 + half;
    uint32_t kdst0 = (uint32_t)__cvta_generic_to_shared(ksm + (size_t)H * 128 + sub * 8);
    uint32_t vdst0 = (uint32_t)__cvta_generic_to_shared(vsm + (size_t)H * 128 + sub * 8);

    auto copy_stage = [&](int st, int step) {
        int k = step * 32 + H;
        const float* kp = Kb + (size_t)k * (NKV * HD) + sub * 8;
        const float* vp = Vb + (size_t)k * (NKV * HD) + sub * 8;
        uint32_t kd = kdst0 + st * (32 * 128 * 4);
        uint32_t vd = vdst0 + st * (32 * 128 * 4);
        CP16(kd, kp);       CP16(kd + 16, kp + 4);
        CP16(vd, vp);       CP16(vd + 16, vp + 4);
    };

    #pragma unroll
    for (int s = 0; s < STAGES; s++) { copy_stage(s, s); CPCOMMIT(); }

    ull acc[4][2] = {};
    float ssum[4] = {0.f, 0.f, 0.f, 0.f};

    auto process = [&](ulonglong2 kx, ulonglong2 vx) {
        float p[4];
        #pragma unroll
        for (int r2 = 0; r2 < 4; r2++) {
            ull tq = fmul2(q2[r2][0], kx.x);
            tq = ffma2(q2[r2][1], kx.y, tq);
            float2 f = unpack2(tq);
            p[r2] = f.x + f.y;
        }
        ull p01 = pack2(p[0], p[1]), p23 = pack2(p[2], p[3]);
        #pragma unroll
        for (int m = 1; m <= 16; m <<= 1) {
            p01 = redshfl2(p01, m);
            p23 = redshfl2(p23, m);
        }
        float2 fa = unpack2(p01), fc = unpack2(p23);
        float w0 = __expf(fa.x - 16.0f);
        float w1 = __expf(fa.y - 16.0f);
        float w2 = __expf(fc.x - 16.0f);
        float w3 = __expf(fc.y - 16.0f);
        ssum[0] += w0; ssum[1] += w1; ssum[2] += w2; ssum[3] += w3;
        acc[0][0] = ffma2(pack2(w0, w0), vx.x, acc[0][0]);
        acc[0][1] = ffma2(pack2(w0, w0), vx.y, acc[0][1]);
        acc[1][0] = ffma2(pack2(w1, w1), vx.x, acc[1][0]);
        acc[1][1] = ffma2(pack2(w1, w1), vx.y, acc[1][1]);
        acc[2][0] = ffma2(pack2(w2, w2), vx.x, acc[2][0]);
        acc[2][1] = ffma2(pack2(w2, w2), vx.y, acc[2][1]);
        acc[3][0] = ffma2(pack2(w3, w3), vx.x, acc[3][0]);
        acc[3][1] = ffma2(pack2(w3, w3), vx.y, acc[3][1]);
    };

    #pragma unroll 1
    for (int i = 0; i < SEQ / 32 - 1; i++) {       // 0..126
        CPWAIT3();
        int st = i & (STAGES - 1);
        const float* rowA = ksm + (size_t)(st * 32 + 2 * w) * 128 + lane * 4;
        ulonglong2 kA = *(const ulonglong2*)rowA;
        ulonglong2 kB = *(const ulonglong2*)(rowA + 128);
        const float* vrowA = vsm + (size_t)(st * 32 + 2 * w) * 128 + lane * 4;
        ulonglong2 vA = *(const ulonglong2*)vrowA;
        ulonglong2 vB = *(const ulonglong2*)(vrowA + 128);

        if (i + STAGES < SEQ / 32) copy_stage(st, i + STAGES);
        CPCOMMIT();

        process(kA, vA);
        process(kB, vB);
    }
    // peeled last iteration (i = 127): warp 15's second key is the NEW token
    {
        CPWAIT3();
        int st = 3;
        const float* rowA = ksm + (size_t)(st * 32 + 2 * w) * 128 + lane * 4;
        ulonglong2 kA = *(const ulonglong2*)rowA;
        const float* vrowA = vsm + (size_t)(st * 32 + 2 * w) * 128 + lane * 4;
        ulonglong2 vA = *(const ulonglong2*)vrowA;
        ulonglong2 kB, vB;
        if (w == 15) {
            kB = *(const ulonglong2*)&knvn[lane * 4];
            vB = *(const ulonglong2*)&knvn[128 + lane * 4];
        } else {
            kB = *(const ulonglong2*)(rowA + 128);
            vB = *(const ulonglong2*)(vrowA + 128);
        }
        process(kA, vA);
        process(kB, vB);
    }

    #pragma unroll
    for (int r2 = 0; r2 < 4; r2++) {
        *(ull*)&part[(size_t)w * 512 + r2 * 128 + lane * 4]     = acc[r2][0];
        *(ull*)&part[(size_t)w * 512 + r2 * 128 + lane * 4 + 2] = acc[r2][1];
        if (lane == 0) psum[w * 4 + r2] = ssum[r2];
    }
    __syncthreads();

    float tot = 0.f, ts = 0.f;
    #pragma unroll
    for (int h2 = 0; h2 < 16; h2++) {
        tot += part[(size_t)h2 * 512 + tid];
        ts  += psum[h2 * 4 + r];
    }
    g_attn[(size_t)b * 4096 + g * 512 + tid] = tot / ts;
}

// ---------------- final combine of wo K-split partials ----------------
__global__ void __launch_bounds__(256) combine_out(float* __restrict__ out)
{
    int e = blockIdx.x * 256 + threadIdx.x;
    int b = e >> 12, col = e & 4095;
    const float* p = g_Po + (size_t)(b >> 1) * 8192 + (size_t)col * 2 + (b & 1);
    float v = 0.f;
    #pragma unroll
    for (int ks = 0; ks < KSPLIT; ks++) v += p[(size_t)ks * 8 * 8192];
    out[e] = v;
}

// ---------------- launch ----------------
extern "C" void kernel_launch(void* const* d_in, const int* in_sizes, int n_in,
                              void* d_out, int out_size)
{
    const float* x  = (const float*)d_in[0];
    const float* wq = (const float*)d_in[1];
    const float* wk = (const float*)d_in[2];
    const float* wv = (const float*)d_in[3];
    const float* wo = (const float*)d_in[4];
    const float* ck = (const float*)d_in[5];
    const float* cv = (const float*)d_in[6];

    const int attn_smem = (STAGES * 32 * 128 * 2 + 16 * 512 + 64 + 256 + 512) * 4;  // ~167KB
    const int gemm_smem = NSTG * SROWS * 2048 + KSLICE * 64 + NSTG * 16 + 128;      // ~96.5KB
    static int smem_set = 0;
    if (!smem_set) {
        cudaFuncSetAttribute(attention, cudaFuncAttributeMaxDynamicSharedMemorySize, attn_smem);
        cudaFuncSetAttribute(gemm16, cudaFuncAttributeMaxDynamicSharedMemorySize, gemm_smem);
        smem_set = 1;
    }

    gemm16<<<dim3(12, KSPLIT), 160, gemm_smem>>>(x, wq, wk, wv, 0);
    attention<<<dim3(8, 16), 512, attn_smem>>>(ck, cv);
    gemm16<<<dim3(8, KSPLIT), 160, gemm_smem>>>(x, wo, wo, wo, 1);
    combine_out<<<256, 256>>>((float*)d_out);
}